// round 14
// baseline (speedup 1.0000x reference)
#include <cuda_runtime.h>
#include <cuda_bf16.h>

// Shapes (fixed by the problem)
#define B_  32
#define N_  8
#define LQ_ 256
#define LD_ 512
#define D_  768

#define D4_       (D_ / 4)              // 192 float4 per row
#define TOT_ROWS_ (B_ * N_ * LD_)       // 131072 doc rows total

// Persistent single-wave geometry: 148 SMs x 5 blocks = 740 blocks
#define GRID_T_    740
#define BLK_T_     D4_                  // 192 threads; threadIdx.x == d4
#define PREP_BLKS_ 256
#define NCHUNK_    8
#define CROWS_     (LQ_ / NCHUNK_)      // 32 question rows per prep chunk

// Byte-balanced row partition (prep chunk ~ 32 row-equivalents):
//   blocks [0,256):    156 rows each, start = i*156
//   blocks [256,596):  188 rows each, start = 39936 + (i-256)*188
//   blocks [596,740):  189 rows each, start = 103856 + (i-596)*189
// 256*156 + 340*188 + 144*189 = 131072 exactly.

// Scratch (no cudaMalloc allowed). Counters zero-init, self-cleaned by the
// last ticketed block -> graph-replay safe.
__device__ float4 g_qpart4[NCHUNK_][B_][D4_];
__device__ float  g_sign[B_ * N_];
__device__ double g_acc;
__device__ unsigned int g_ticket;
__device__ unsigned int g_prep_done;

__global__ void __launch_bounds__(BLK_T_, 5) fused_kernel(
        const float4* __restrict__ q,
        const float4* __restrict__ docs,
        const unsigned char* __restrict__ isa,
        float* __restrict__ out) {

    const int bid = blockIdx.x;
    const int d4  = threadIdx.x;        // 0..191

    // ----------------- prep role (blocks 0..255, then fall through) --------
    if (bid < PREP_BLKS_) {
        if (bid == 0) {
            // Decode is_ans; dtype sniffed (int32 / float32 / uint8) from the
            // first 256 bytes, in-bounds under every candidate encoding.
            __shared__ int enc;
            if (threadIdx.x == 0) {
                const unsigned int* w = (const unsigned int*)isa;
                bool all01 = true, allf = true;
                for (int i = 0; i < (B_ * N_) / 4; ++i) {
                    unsigned int v = w[i];
                    if (v != 0u && v != 1u)           all01 = false;
                    if (v != 0u && v != 0x3F800000u)  allf  = false;
                }
                enc = all01 ? 0 : (allf ? 1 : 2);
            }
            __syncthreads();
            for (int i = threadIdx.x; i < B_ * N_; i += BLK_T_) {
                bool ans;
                if (enc == 0)      ans = ((const int*)isa)[i]   != 0;
                else if (enc == 1) ans = ((const float*)isa)[i] != 0.0f;
                else               ans = isa[i]                 != 0;
                g_sign[i] = ans ? -1.0f : 1.0f;
            }
        }

        int b = bid >> 3;               // 0..31
        int c = bid & 7;                // 0..7
        const float4* base = q + ((size_t)b * LQ_ + (size_t)c * CROWS_) * D4_ + d4;

        float4 s = make_float4(0.f, 0.f, 0.f, 0.f);
#pragma unroll 8
        for (int l = 0; l < CROWS_; ++l) {
            float4 v = __ldcs(base + (size_t)l * D4_);
            s.x += v.x; s.y += v.y; s.z += v.z; s.w += v.w;
        }
        g_qpart4[c][b][d4] = s;

        __syncthreads();                // all block writes (incl. sign) done
        __threadfence();
        if (threadIdx.x == 0)
            atomicAdd(&g_prep_done, 1u);
        __syncthreads();                // keep block converged before docs
    }

    // ----------------- docs role (all 740 blocks) --------------------------
    int row_start, row_cnt;
    if (bid < 256)      { row_start = bid * 156;                  row_cnt = 156; }
    else if (bid < 596) { row_start = 39936 + (bid - 256) * 188;  row_cnt = 188; }
    else                { row_start = 103856 + (bid - 596) * 189; row_cnt = 189; }

    // Raw per-segment column sums (a block range spans at most 2 slabs).
    float4 seg_sv[2];
    int    seg_bn[2];
    int    nseg = 0;

    int r = row_start;
    int remaining = row_cnt;
    while (remaining > 0) {
        int bn      = r >> 9;                        // 512 rows per slab
        int seg_end = ((bn + 1) << 9);
        if (seg_end > r + remaining) seg_end = r + remaining;
        int cnt = seg_end - r;

        const float4* p = docs + (size_t)r * D4_ + d4;

        float4 a0 = make_float4(0.f, 0.f, 0.f, 0.f);
        float4 a1 = make_float4(0.f, 0.f, 0.f, 0.f);
        float4 a2 = make_float4(0.f, 0.f, 0.f, 0.f);
        float4 a3 = make_float4(0.f, 0.f, 0.f, 0.f);

        int m = 0;
        for (; m + 8 <= cnt; m += 8) {
            float4 v0 = __ldcs(p);
            float4 v1 = __ldcs(p + 1 * D4_);
            float4 v2 = __ldcs(p + 2 * D4_);
            float4 v3 = __ldcs(p + 3 * D4_);
            float4 v4 = __ldcs(p + 4 * D4_);
            float4 v5 = __ldcs(p + 5 * D4_);
            float4 v6 = __ldcs(p + 6 * D4_);
            float4 v7 = __ldcs(p + 7 * D4_);
            p += 8 * D4_;
            a0.x += v0.x; a0.y += v0.y; a0.z += v0.z; a0.w += v0.w;
            a1.x += v1.x; a1.y += v1.y; a1.z += v1.z; a1.w += v1.w;
            a2.x += v2.x; a2.y += v2.y; a2.z += v2.z; a2.w += v2.w;
            a3.x += v3.x; a3.y += v3.y; a3.z += v3.z; a3.w += v3.w;
            a0.x += v4.x; a0.y += v4.y; a0.z += v4.z; a0.w += v4.w;
            a1.x += v5.x; a1.y += v5.y; a1.z += v5.z; a1.w += v5.w;
            a2.x += v6.x; a2.y += v6.y; a2.z += v6.z; a2.w += v6.w;
            a3.x += v7.x; a3.y += v7.y; a3.z += v7.z; a3.w += v7.w;
        }
        for (; m < cnt; ++m) {
            float4 v = __ldcs(p);
            p += D4_;
            a0.x += v.x; a0.y += v.y; a0.z += v.z; a0.w += v.w;
        }

        float4 sv;
        sv.x = (a0.x + a1.x) + (a2.x + a3.x);
        sv.y = (a0.y + a1.y) + (a2.y + a3.y);
        sv.z = (a0.z + a1.z) + (a2.z + a3.z);
        sv.w = (a0.w + a1.w) + (a2.w + a3.w);
        seg_sv[nseg] = sv;
        seg_bn[nseg] = bn;
        ++nseg;

        r = seg_end;
        remaining -= cnt;
    }

    // Wait for prep (finishes early in the single wave; effectively free).
    if (threadIdx.x == 0) {
        while (*(volatile unsigned int*)&g_prep_done != PREP_BLKS_)
            __nanosleep(64);
    }
    __syncthreads();
    __threadfence();

    // Fold qsum partials + sign per segment, dot with raw column sums.
    float acc = 0.f;
    for (int s = 0; s < nseg; ++s) {
        int bn = seg_bn[s];
        int b  = bn >> 3;
        float4 qs = make_float4(0.f, 0.f, 0.f, 0.f);
#pragma unroll
        for (int c = 0; c < NCHUNK_; ++c) {
            float4 pv = g_qpart4[c][b][d4];
            qs.x += pv.x; qs.y += pv.y; qs.z += pv.z; qs.w += pv.w;
        }
        float4 sv = seg_sv[s];
        acc += (sv.x * qs.x + sv.y * qs.y + sv.z * qs.z + sv.w * qs.w)
             * g_sign[bn];
    }

    // warp reduce (6 warps per block)
#pragma unroll
    for (int o = 16; o > 0; o >>= 1)
        acc += __shfl_down_sync(0xFFFFFFFFu, acc, o);

    __shared__ float warp_sums[BLK_T_ / 32];
    int lane = threadIdx.x & 31;
    int wid  = threadIdx.x >> 5;
    if (lane == 0) warp_sums[wid] = acc;
    __syncthreads();

    __shared__ bool s_last;
    if (threadIdx.x == 0) {
        float v = warp_sums[0];
#pragma unroll
        for (int w = 1; w < BLK_T_ / 32; ++w) v += warp_sums[w];
        atomicAdd(&g_acc, (double)v);
        __threadfence();
        unsigned int t = atomicAdd(&g_ticket, 1u);
        s_last = (t == GRID_T_ - 1);
    }
    __syncthreads();

    if (s_last && threadIdx.x == 0) {
        __threadfence();
        out[0] = (float)(g_acc * (1.0 / ((double)LQ_ * (double)LD_)));
        // Self-clean for the next graph replay.
        g_acc = 0.0;
        g_ticket = 0u;
        g_prep_done = 0u;
        __threadfence();
    }
}

extern "C" void kernel_launch(void* const* d_in, const int* in_sizes, int n_in,
                              void* d_out, int out_size) {
    const float*         questions = (const float*)d_in[0];
    const float*         docs      = (const float*)d_in[1];
    const unsigned char* is_ans    = (const unsigned char*)d_in[2];
    float* out = (float*)d_out;
    (void)in_sizes; (void)n_in; (void)out_size;

    fused_kernel<<<GRID_T_, BLK_T_>>>((const float4*)questions,
                                      (const float4*)docs, is_ans, out);
}

// round 15
// speedup vs baseline: 1.0304x; 1.0304x over previous
#include <cuda_runtime.h>
#include <cuda_bf16.h>

// Shapes (fixed by the problem)
#define B_  32
#define N_  8
#define LQ_ 256
#define LD_ 512
#define D_  768

#define D4_         (D_ / 4)            // 192 float4 per row
#define BN_STRIDE4_ (LD_ * D4_)         // float4 per (b,n) slab = 98304

// Fused-kernel geometry (converged optimum)
#define PREP_BLKS_     (B_ * 8)                   // 256 prep blocks (b, chunk)
#define NCHUNK_        8
#define CROWS_         (LQ_ / NCHUNK_)            // 32 question rows per chunk
#define BLKS_PER_SLAB_ 8
#define ROWS_PER_BLK_  (LD_ / BLKS_PER_SLAB_)     // 64 doc rows per block
#define DOCS_BLKS_     (B_ * N_ * BLKS_PER_SLAB_) // 2048
#define GRID_T_        (PREP_BLKS_ + DOCS_BLKS_)  // 2304
#define BLK_T_         D4_                        // 192 threads

// Scratch (no cudaMalloc allowed). Counters are zero-initialized and
// self-cleaned by the last ticketed block -> graph-replay safe.
__device__ float4 g_qpart4[NCHUNK_][B_][D4_];
__device__ float  g_sign[B_ * N_];
__device__ double g_acc;
__device__ unsigned int g_ticket;
__device__ unsigned int g_prep_done;

// ---------------------------------------------------------------------------
// Single fused kernel (FINAL — R11 configuration).
//   Blocks [0, 256):    prep — decode is_ans (block 0 only) + partial qsum
//                       for (b, chunk). Streams 25 MB of questions.
//   Blocks [256, 2304): docs — raw column sums over a 64-row sub-slab
//                       (402 MB stream, no dependency on prep). Epilogue
//                       spins until prep counter hits 256 (long since done),
//                       folds qsum, dots, reduces, tickets. Last ticket
//                       writes the scalar and resets all counters.
// __launch_bounds__(192, 5): 5 resident blocks per SM (5 independent slab
// streams, ~30 KB outstanding per SM). Multi-wave (3.1 waves) deliberately
// kept: wave transitions self-balance the between-SM latency spread that a
// single-wave static partition exposes (R14 measured 1.9 us slower).
// ---------------------------------------------------------------------------
__global__ void __launch_bounds__(BLK_T_, 5) fused_kernel(
        const float4* __restrict__ q,
        const float4* __restrict__ docs,
        const unsigned char* __restrict__ isa,
        float* __restrict__ out) {

    if (blockIdx.x < PREP_BLKS_) {
        // ----------------- prep role -----------------
        if (blockIdx.x == 0) {
            // Decode is_ans; dtype sniffed (int32 / float32 / uint8) from the
            // first 256 bytes, in-bounds under every candidate encoding.
            __shared__ int enc;
            if (threadIdx.x == 0) {
                const unsigned int* w = (const unsigned int*)isa;
                bool all01 = true, allf = true;
                for (int i = 0; i < (B_ * N_) / 4; ++i) {
                    unsigned int v = w[i];
                    if (v != 0u && v != 1u)           all01 = false;
                    if (v != 0u && v != 0x3F800000u)  allf  = false;
                }
                enc = all01 ? 0 : (allf ? 1 : 2);
            }
            __syncthreads();
            for (int i = threadIdx.x; i < B_ * N_; i += BLK_T_) {
                bool ans;
                if (enc == 0)      ans = ((const int*)isa)[i]   != 0;
                else if (enc == 1) ans = ((const float*)isa)[i] != 0.0f;
                else               ans = isa[i]                 != 0;
                g_sign[i] = ans ? -1.0f : 1.0f;
            }
        }

        int b  = blockIdx.x >> 3;         // 0..31
        int c  = blockIdx.x & 7;          // 0..7
        int d4 = threadIdx.x;             // 0..191
        const float4* base = q + ((size_t)b * LQ_ + (size_t)c * CROWS_) * D4_ + d4;

        float4 s = make_float4(0.f, 0.f, 0.f, 0.f);
#pragma unroll 8
        for (int l = 0; l < CROWS_; ++l) {
            float4 v = __ldcs(base + (size_t)l * D4_);
            s.x += v.x; s.y += v.y; s.z += v.z; s.w += v.w;
        }
        g_qpart4[c][b][d4] = s;

        __syncthreads();                  // all block writes (incl. sign) done
        __threadfence();
        if (threadIdx.x == 0)
            atomicAdd(&g_prep_done, 1u);
        return;
    }

    // ----------------- docs role -----------------
    const int idx  = blockIdx.x - PREP_BLKS_;
    const int bn   = idx >> 3;                    // 0..255
    const int b    = bn >> 3;
    const int d4   = threadIdx.x;                 // 0..191
    const int row0 = (idx & 7) * ROWS_PER_BLK_;

    const float4* p = docs + (size_t)bn * BN_STRIDE4_
                           + (size_t)row0 * D4_ + d4;

    // Raw (unweighted) column sums — no dependency on prep.
    float4 a0 = make_float4(0.f, 0.f, 0.f, 0.f);
    float4 a1 = make_float4(0.f, 0.f, 0.f, 0.f);
    float4 a2 = make_float4(0.f, 0.f, 0.f, 0.f);
    float4 a3 = make_float4(0.f, 0.f, 0.f, 0.f);

    for (int m = 0; m < ROWS_PER_BLK_; m += 8) {
        float4 v0 = __ldcs(p);
        float4 v1 = __ldcs(p + 1 * D4_);
        float4 v2 = __ldcs(p + 2 * D4_);
        float4 v3 = __ldcs(p + 3 * D4_);
        float4 v4 = __ldcs(p + 4 * D4_);
        float4 v5 = __ldcs(p + 5 * D4_);
        float4 v6 = __ldcs(p + 6 * D4_);
        float4 v7 = __ldcs(p + 7 * D4_);
        p += 8 * D4_;
        a0.x += v0.x; a0.y += v0.y; a0.z += v0.z; a0.w += v0.w;
        a1.x += v1.x; a1.y += v1.y; a1.z += v1.z; a1.w += v1.w;
        a2.x += v2.x; a2.y += v2.y; a2.z += v2.z; a2.w += v2.w;
        a3.x += v3.x; a3.y += v3.y; a3.z += v3.z; a3.w += v3.w;
        a0.x += v4.x; a0.y += v4.y; a0.z += v4.z; a0.w += v4.w;
        a1.x += v5.x; a1.y += v5.y; a1.z += v5.z; a1.w += v5.w;
        a2.x += v6.x; a2.y += v6.y; a2.z += v6.z; a2.w += v6.w;
        a3.x += v7.x; a3.y += v7.y; a3.z += v7.z; a3.w += v7.w;
    }
    float4 sv;
    sv.x = (a0.x + a1.x) + (a2.x + a3.x);
    sv.y = (a0.y + a1.y) + (a2.y + a3.y);
    sv.z = (a0.z + a1.z) + (a2.z + a3.z);
    sv.w = (a0.w + a1.w) + (a2.w + a3.w);

    // Wait for prep (done ~5us into a ~64us stream; effectively free).
    if (threadIdx.x == 0) {
        while (*(volatile unsigned int*)&g_prep_done != PREP_BLKS_)
            __nanosleep(64);
    }
    __syncthreads();
    __threadfence();

    // Fold qsum partials + sign, then dot with the raw column sum.
    float4 qs = make_float4(0.f, 0.f, 0.f, 0.f);
#pragma unroll
    for (int c = 0; c < NCHUNK_; ++c) {
        float4 pv = g_qpart4[c][b][d4];
        qs.x += pv.x; qs.y += pv.y; qs.z += pv.z; qs.w += pv.w;
    }
    float acc = (sv.x * qs.x + sv.y * qs.y + sv.z * qs.z + sv.w * qs.w)
              * g_sign[bn];

    // warp reduce (6 warps per block)
#pragma unroll
    for (int o = 16; o > 0; o >>= 1)
        acc += __shfl_down_sync(0xFFFFFFFFu, acc, o);

    __shared__ float warp_sums[BLK_T_ / 32];
    int lane = threadIdx.x & 31;
    int wid  = threadIdx.x >> 5;
    if (lane == 0) warp_sums[wid] = acc;
    __syncthreads();

    __shared__ bool s_last;
    if (threadIdx.x == 0) {
        float v = warp_sums[0];
#pragma unroll
        for (int w = 1; w < BLK_T_ / 32; ++w) v += warp_sums[w];
        atomicAdd(&g_acc, (double)v);
        __threadfence();
        unsigned int t = atomicAdd(&g_ticket, 1u);
        s_last = (t == DOCS_BLKS_ - 1);
    }
    __syncthreads();

    if (s_last && threadIdx.x == 0) {
        __threadfence();
        out[0] = (float)(g_acc * (1.0 / ((double)LQ_ * (double)LD_)));
        // Self-clean for the next graph replay.
        g_acc = 0.0;
        g_ticket = 0u;
        g_prep_done = 0u;
        __threadfence();
    }
}

extern "C" void kernel_launch(void* const* d_in, const int* in_sizes, int n_in,
                              void* d_out, int out_size) {
    const float*         questions = (const float*)d_in[0];
    const float*         docs      = (const float*)d_in[1];
    const unsigned char* is_ans    = (const unsigned char*)d_in[2];
    float* out = (float*)d_out;
    (void)in_sizes; (void)n_in; (void)out_size;

    fused_kernel<<<GRID_T_, BLK_T_>>>((const float4*)questions,
                                      (const float4*)docs, is_ans, out);
}